// round 16
// baseline (speedup 1.0000x reference)
#include <cuda_runtime.h>
#include <cuda_bf16.h>
#include <cstdint>

#define N_NODES 63
#define C_CLASSES 100
#define B_TOT 8192
#define D_DIM 512
#define NTN 4096

// ---------------- device scratch ----------------
__device__ __nv_bfloat16 g_xh[B_TOT * D_DIM], g_xl[B_TOT * D_DIM];
__device__ __nv_bfloat16 g_wh[NTN * D_DIM], g_wl[NTN * D_DIM];
__device__ __nv_bfloat16 g_m[128 * NTN];                    // rows >=100 stay zero
__device__ __nv_bfloat16 g_lp[(size_t)B_TOT * NTN];

// ---------------- helpers ----------------
__device__ __forceinline__ uint32_t s2u(const void* p) {
    uint32_t a;
    asm("{ .reg .u64 t; cvta.to.shared.u64 t, %1; cvt.u32.u64 %0, t; }" : "=r"(a) : "l"(p));
    return a;
}
#define CP_COMMIT() asm volatile("cp.async.commit_group;" ::: "memory")
#define CP_WAIT(n)  asm volatile("cp.async.wait_group %0;" :: "n"(n) : "memory")
__device__ __forceinline__ void cp16(uint32_t dst, const void* src) {
    asm volatile("cp.async.cg.shared.global [%0], [%1], 16;" :: "r"(dst), "l"(src) : "memory");
}
// generic staged tile (gemm2): 256 threads
__device__ __forceinline__ void stage_tile(uint32_t dstBase, const char* src, size_t rowB, int nRows) {
    const int units = nRows * 8;
    for (int u = threadIdx.x; u < units; u += 256) {
        int r = u >> 3, cu = u & 7;
        cp16(dstBase + (uint32_t)(((r << 3) + (cu ^ (r & 7))) << 4), src + (size_t)r * rowB + (cu << 4));
    }
}

#define LDSM4(a, addr) asm volatile( \
    "ldmatrix.sync.aligned.m8n8.x4.shared.b16 {%0,%1,%2,%3}, [%4];" \
    : "=r"((a)[0]), "=r"((a)[1]), "=r"((a)[2]), "=r"((a)[3]) : "r"(addr))
#define LDSM2(b, addr) asm volatile( \
    "ldmatrix.sync.aligned.m8n8.x2.shared.b16 {%0,%1}, [%2];" \
    : "=r"((b)[0]), "=r"((b)[1]) : "r"(addr))
#define MMA(c, a, b0, b1) asm volatile( \
    "mma.sync.aligned.m16n8k16.row.col.f32.bf16.bf16.f32 " \
    "{%0,%1,%2,%3},{%4,%5,%6,%7},{%8,%9},{%0,%1,%2,%3};" \
    : "+f"((c)[0]), "+f"((c)[1]), "+f"((c)[2]), "+f"((c)[3]) \
    : "r"((a)[0]), "r"((a)[1]), "r"((a)[2]), "r"((a)[3]), "r"(b0), "r"(b1))

// ============ prep ============
// fused x+w split: indices [0, 4M) -> x, [4M, 6M) -> w
__global__ void prep_xw(const float* __restrict__ x, const float* __restrict__ W) {
    int i = blockIdx.x * 256 + threadIdx.x;
    if (i < B_TOT * D_DIM) {
        float v = x[i];
        __nv_bfloat16 h = __float2bfloat16(v);
        g_xh[i] = h;
        g_xl[i] = __float2bfloat16(v - __bfloat162float(h));
    } else {
        int j = i - B_TOT * D_DIM;
        int row = j >> 9, k = j & 511, t = row >> 6, n = row & 63;
        float v = (n < N_NODES) ? W[((size_t)t * N_NODES + n) * D_DIM + k] : 0.f;
        __nv_bfloat16 h = __float2bfloat16(v);
        g_wh[j] = h;
        g_wl[j] = __float2bfloat16(v - __bfloat162float(h));
    }
}
__global__ void prep_m(const float* __restrict__ ll, const float* __restrict__ tw) {
    int row = blockIdx.x * 8 + (threadIdx.x >> 5);   // t*64 + l
    int lane = threadIdx.x & 31;
    const float* src = ll + (size_t)row * C_CLASSES;
    float v[4];
#pragma unroll
    for (int q = 0; q < 4; ++q) { int c = lane + 32 * q; v[q] = (c < C_CLASSES) ? src[c] : -1e30f; }
    float mx = fmaxf(fmaxf(v[0], v[1]), fmaxf(v[2], v[3]));
#pragma unroll
    for (int o = 16; o; o >>= 1) mx = fmaxf(mx, __shfl_xor_sync(~0u, mx, o));
    float e[4], s = 0.f;
#pragma unroll
    for (int q = 0; q < 4; ++q) { int c = lane + 32 * q; e[q] = (c < C_CLASSES) ? __expf(v[q] - mx) : 0.f; s += e[q]; }
#pragma unroll
    for (int o = 16; o; o >>= 1) s += __shfl_xor_sync(~0u, s, o);
    float scale = tw[row >> 6] / s;
#pragma unroll
    for (int q = 0; q < 4; ++q) {
        int c = lane + 32 * q;
        if (c < C_CLASSES) g_m[(size_t)c * NTN + row] = __float2bfloat16(e[q] * scale);
    }
}

// ============ GEMM1 fused 3-pass + sigmoid + leaf product (R12, unchanged) ============
#define G1_AOFF 1024
#define G1_ASL  16384
#define G1_BOFF (1024 + 3 * G1_ASL)          // 50176
#define G1_BSL  32768
#define G1_SMEM (G1_BOFF + 2 * G1_BSL)       // 115712

__global__ void __launch_bounds__(256, 2) gemm1_kernel(const float* __restrict__ bias) {
    extern __shared__ char smem[];
    const uint32_t sb = s2u(smem);
    const int tid = threadIdx.x, wid = tid >> 5, lane = tid & 31;
    const int b0 = blockIdx.x * 128, ntb = blockIdx.y;

    if (tid < 126) {
        int tt = tid / 63, n = tid % 63;
        ((float*)smem)[tt * 64 + n] = bias[(ntb * 2 + tt) * N_NODES + n];
    }

    const char* srcXh = (const char*)g_xh + (size_t)b0 * 1024;
    const char* srcXl = (const char*)g_xl + (size_t)b0 * 1024;
    const char* srcWh = (const char*)g_wh + (size_t)(ntb * 128) * 1024;
    const char* srcWl = (const char*)g_wl + (size_t)(ntb * 128) * 1024;

#define STAGE_A(hc, slotB) do {                                                    \
    _Pragma("unroll") for (int _i = 0; _i < 2; ++_i) {                             \
        int _id = tid + _i * 256, _m = _id >> 2, _u = _id & 3;                     \
        uint32_t _d = (uint32_t)(_m * 64 + ((_u ^ ((_m >> 1) & 3)) << 4));         \
        size_t _s = (size_t)_m * 1024 + (size_t)(hc) * 64 + (_u << 4);             \
        cp16((slotB) + _d, srcXh + _s);                                            \
        cp16((slotB) + 8192 + _d, srcXl + _s);                                     \
    } } while (0)
#define STAGE_B(c, slotB) do {                                                     \
    _Pragma("unroll") for (int _i = 0; _i < 4; ++_i) {                             \
        int _id = tid + _i * 256, _r = _id >> 3, _cu = _id & 7;                    \
        uint32_t _d = (uint32_t)(_r * 128 + ((_cu ^ (_r & 7)) << 4));              \
        size_t _s = (size_t)_r * 1024 + (size_t)(c) * 128 + (_cu << 4);            \
        cp16((slotB) + _d, srcWh + _s);                                            \
        cp16((slotB) + 16384 + _d, srcWl + _s);                                    \
    } } while (0)

    const int wm = wid & 3, wn = wid >> 2;
    const int m0w = wm * 32, n0w = wn * 64;
    const uint32_t sx = lane & 7;
    const uint32_t bKh = (lane >> 3) & 1;
    const uint32_t kh4 = ((lane >> 4) & 1) << 4;
    uint32_t PA[2];
#pragma unroll
    for (int mt = 0; mt < 2; ++mt) {
        int row = m0w + mt * 16 + (lane & 15);
        PA[mt] = (uint32_t)(row * 64 + (((row >> 1) & 3) << 4));
    }
    uint32_t rB[4];
#pragma unroll
    for (int np = 0; np < 4; ++np)
        rB[np] = (uint32_t)(n0w + np * 16 + (lane & 7) + ((lane & 16) >> 1)) * 128;

    float acc[2][8][4];
#pragma unroll
    for (int mt = 0; mt < 2; ++mt)
#pragma unroll
        for (int nf = 0; nf < 8; ++nf)
#pragma unroll
            for (int q = 0; q < 4; ++q) acc[mt][nf][q] = 0.f;

    STAGE_A(0, sb + G1_AOFF);
    STAGE_B(0, sb + G1_BOFF);
    CP_COMMIT();
    STAGE_A(1, sb + G1_AOFF + G1_ASL);
    CP_COMMIT();

    uint32_t aComp = sb + G1_AOFF;
    uint32_t aStage = sb + G1_AOFF + 2 * G1_ASL;
    const uint32_t aLo = sb + G1_AOFF, aHi = sb + G1_AOFF + 2 * G1_ASL;

#pragma unroll 1
    for (int h = 0; h < 16; ++h) {
        CP_WAIT(1);
        __syncthreads();
        if (h <= 13) STAGE_A(h + 2, aStage);
        if (!(h & 1) && h <= 12) STAGE_B((h >> 1) + 1, sb + G1_BOFF + ((((h >> 1) + 1) & 1) ? G1_BSL : 0));
        CP_COMMIT();

        const uint32_t Ah = aComp, Al = aComp + 8192;
        const uint32_t Bb = sb + G1_BOFF + (((h >> 1) & 1) ? G1_BSL : 0);
        const uint32_t kbase = (uint32_t)(h & 1) * 2;

#pragma unroll
        for (int ks = 0; ks < 2; ++ks) {
            const uint32_t uoA = (((uint32_t)ks << 5) + kh4);
            uint32_t ah[2][4], al[2][4];
            LDSM4(ah[0], Ah + (PA[0] ^ uoA));
            LDSM4(ah[1], Ah + (PA[1] ^ uoA));
            LDSM4(al[0], Al + (PA[0] ^ uoA));
            LDSM4(al[1], Al + (PA[1] ^ uoA));

            const uint32_t koB = (((kbase + (uint32_t)ks) * 2 + bKh) ^ sx) << 4;
            uint32_t bh[4][4];
#pragma unroll
            for (int np = 0; np < 4; ++np) LDSM4(bh[np], Bb + rB[np] + koB);
#pragma unroll
            for (int mt = 0; mt < 2; ++mt)
#pragma unroll
                for (int np = 0; np < 4; ++np) {
                    MMA(acc[mt][np * 2],     ah[mt], bh[np][0], bh[np][1]);
                    MMA(acc[mt][np * 2 + 1], ah[mt], bh[np][2], bh[np][3]);
                }
#pragma unroll
            for (int mt = 0; mt < 2; ++mt)
#pragma unroll
                for (int np = 0; np < 4; ++np) {
                    MMA(acc[mt][np * 2],     al[mt], bh[np][0], bh[np][1]);
                    MMA(acc[mt][np * 2 + 1], al[mt], bh[np][2], bh[np][3]);
                }
            uint32_t bl[4][4];
#pragma unroll
            for (int np = 0; np < 4; ++np) LDSM4(bl[np], Bb + 16384 + rB[np] + koB);
#pragma unroll
            for (int mt = 0; mt < 2; ++mt)
#pragma unroll
                for (int np = 0; np < 4; ++np) {
                    MMA(acc[mt][np * 2],     ah[mt], bl[np][0], bl[np][1]);
                    MMA(acc[mt][np * 2 + 1], ah[mt], bl[np][2], bl[np][3]);
                }
        }
        aComp  = (aComp  == aHi) ? aLo : aComp + G1_ASL;
        aStage = (aStage == aHi) ? aLo : aStage + G1_ASL;
    }

    float* dec = (float*)(smem + G1_AOFF);        // 128 x pitch65 f32
    const float* bsm = (const float*)smem;
    const int r4 = lane >> 2, c2 = (lane & 3) * 2;

#pragma unroll 1
    for (int t = 0; t < 2; ++t) {
        __syncthreads();
        if (wn == t) {
#pragma unroll
            for (int mt = 0; mt < 2; ++mt)
#pragma unroll
                for (int nf = 0; nf < 8; ++nf) {
                    int row = m0w + mt * 16 + r4, col = nf * 8 + c2;
                    dec[row * 65 + col]           = acc[mt][nf][0];
                    dec[row * 65 + col + 1]       = acc[mt][nf][1];
                    dec[(row + 8) * 65 + col]     = acc[mt][nf][2];
                    dec[(row + 8) * 65 + col + 1] = acc[mt][nf][3];
                }
        }
        __syncthreads();
        {
            const int row = tid & 127, hh = tid >> 7;
            const float* dr = dec + row * 65;
            const float* bs = bsm + t * 64;
            float dc[63];
#pragma unroll
            for (int n = 0; n < 63; ++n)
                dc[n] = __fdividef(1.f, 1.f + __expf(-(dr[n] + bs[n])));
            float p[32];
            p[0] = hh ? dc[0] : (1.f - dc[0]);
#pragma unroll
            for (int d = 1; d < 6; ++d)
#pragma unroll
                for (int i = (1 << (d - 1)) - 1; i >= 0; --i) {
                    float v = dc[(1 << d) - 1 + hh * (1 << (d - 1)) + i], pi = p[i];
                    p[2 * i + 1] = pi * v;
                    p[2 * i]     = pi * (1.f - v);
                }
            __nv_bfloat16 ob[32];
#pragma unroll
            for (int l = 0; l < 32; ++l) ob[l] = __float2bfloat16(p[l]);
            uint4* dst = (uint4*)(g_lp + (size_t)(b0 + row) * NTN + (ntb * 2 + t) * 64 + hh * 32);
            const uint4* srcv = (const uint4*)ob;
#pragma unroll
            for (int q = 0; q < 4; ++q) dst[q] = srcv[q];
        }
    }
}

// ============ GEMM2: out = lp @ M^T, full K per CTA (no split, no reduce) ============
// grid 128: 64 batch rows x 128 classes (>=100 dropped). 8 warps (2m x 4n), warp 32x32.
// K = 4096 = 64 segments x 64 k.
#define G2_SOFF 1024
#define G2_BUF  24576                       // A 8KB + B 16KB
#define G2_SMEM (G2_SOFF + 2 * G2_BUF)      // 50176
#define G2_NSEG 64

__global__ void __launch_bounds__(256) gemm2_kernel(float* __restrict__ out) {
    extern __shared__ char smem[];
    const uint32_t sb = s2u(smem);
    const int tid = threadIdx.x, wid = tid >> 5, lane = tid & 31;
    const int b0 = blockIdx.x * 64;

    const char* Ag = (const char*)g_lp + (size_t)b0 * 8192;
    const char* Bg = (const char*)g_m;

#define G2_SEG(seg) do { uint32_t _b = sb + G2_SOFF + ((seg) & 1) * G2_BUF; \
    stage_tile(_b, Ag + (size_t)(seg) * 128, 8192, 64); \
    stage_tile(_b + 8192, Bg + (size_t)(seg) * 128, 8192, 128); \
    CP_COMMIT(); } while (0)

    const int wm = wid >> 2, wn = wid & 3;
    const int m0w = wm * 32, n0w = wn * 32;
    const uint32_t sx = lane & 7;
    const uint32_t aKh = (lane >> 4) & 1, bKh = (lane >> 3) & 1;
    uint32_t rA[2], rB[4];
#pragma unroll
    for (int mt = 0; mt < 2; ++mt) rA[mt] = (uint32_t)(m0w + mt * 16 + (lane & 15)) * 128;
#pragma unroll
    for (int nt = 0; nt < 4; ++nt) rB[nt] = (uint32_t)(n0w + nt * 8 + (lane & 7)) * 128;

    float acc[2][4][4];
#pragma unroll
    for (int mt = 0; mt < 2; ++mt)
#pragma unroll
        for (int nt = 0; nt < 4; ++nt)
#pragma unroll
            for (int q = 0; q < 4; ++q) acc[mt][nt][q] = 0.f;

    G2_SEG(0); G2_SEG(1);
#pragma unroll 1
    for (int seg = 0; seg < G2_NSEG; ++seg) {
        if (seg < G2_NSEG - 1) { CP_WAIT(1); } else { CP_WAIT(0); }
        __syncthreads();
        uint32_t Ab = sb + G2_SOFF + (seg & 1) * G2_BUF;
        uint32_t Bb = Ab + 8192;
#pragma unroll
        for (int ks = 0; ks < 4; ++ks) {
            uint32_t a[2][4], b[4][2];
#pragma unroll
            for (int mt = 0; mt < 2; ++mt)
                LDSM4(a[mt], Ab + rA[mt] + ((((uint32_t)ks * 2 + aKh) ^ sx) << 4));
#pragma unroll
            for (int nt = 0; nt < 4; ++nt)
                LDSM2(b[nt], Bb + rB[nt] + ((((uint32_t)ks * 2 + bKh) ^ sx) << 4));
#pragma unroll
            for (int mt = 0; mt < 2; ++mt)
#pragma unroll
                for (int nt = 0; nt < 4; ++nt)
                    MMA(acc[mt][nt], a[mt], b[nt][0], b[nt][1]);
        }
        __syncthreads();
        if (seg + 2 < G2_NSEG) G2_SEG(seg + 2);
    }

    {
        const int r = lane >> 2, c2 = (lane & 3) * 2;
#pragma unroll
        for (int mt = 0; mt < 2; ++mt)
#pragma unroll
            for (int nt = 0; nt < 4; ++nt) {
                int row = b0 + m0w + mt * 16 + r;
                int col = n0w + nt * 8 + c2;
                if (col < C_CLASSES) {
                    out[(size_t)row * C_CLASSES + col]       = acc[mt][nt][0];
                    out[(size_t)(row + 8) * C_CLASSES + col] = acc[mt][nt][2];
                }
                if (col + 1 < C_CLASSES) {
                    out[(size_t)row * C_CLASSES + col + 1]       = acc[mt][nt][1];
                    out[(size_t)(row + 8) * C_CLASSES + col + 1] = acc[mt][nt][3];
                }
            }
    }
}

// ============ launch ============
extern "C" void kernel_launch(void* const* d_in, const int* in_sizes, int n_in,
                              void* d_out, int out_size) {
    const float* x    = (const float*)d_in[0];
    const float* W    = (const float*)d_in[1];
    const float* bias = (const float*)d_in[2];
    const float* ll   = (const float*)d_in[3];
    const float* tw   = (const float*)d_in[4];
    float* out = (float*)d_out;

    cudaFuncSetAttribute(gemm1_kernel, cudaFuncAttributeMaxDynamicSharedMemorySize, G1_SMEM);
    cudaFuncSetAttribute(gemm2_kernel, cudaFuncAttributeMaxDynamicSharedMemorySize, G2_SMEM);

    prep_xw<<<(B_TOT * D_DIM + NTN * D_DIM) / 256, 256>>>(x, W);
    prep_m<<<512, 256>>>(ll, tw);
    gemm1_kernel<<<dim3(64, 32), 256, G1_SMEM>>>(bias);
    gemm2_kernel<<<128, 256, G2_SMEM>>>(out);
}

// round 17
// speedup vs baseline: 1.0198x; 1.0198x over previous
#include <cuda_runtime.h>
#include <cuda_bf16.h>
#include <cstdint>

#define N_NODES 63
#define C_CLASSES 100
#define B_TOT 8192
#define D_DIM 512
#define NTN 4096

// ---------------- device scratch ----------------
__device__ __nv_bfloat16 g_xh[B_TOT * D_DIM], g_xl[B_TOT * D_DIM];
__device__ __nv_bfloat16 g_wh[NTN * D_DIM], g_wl[NTN * D_DIM];
__device__ __nv_bfloat16 g_m[128 * NTN];                    // rows >=100 stay zero
__device__ __nv_bfloat16 g_lp[(size_t)B_TOT * NTN];

// ---------------- helpers ----------------
__device__ __forceinline__ uint32_t s2u(const void* p) {
    uint32_t a;
    asm("{ .reg .u64 t; cvta.to.shared.u64 t, %1; cvt.u32.u64 %0, t; }" : "=r"(a) : "l"(p));
    return a;
}
#define CP_COMMIT() asm volatile("cp.async.commit_group;" ::: "memory")
#define CP_WAIT(n)  asm volatile("cp.async.wait_group %0;" :: "n"(n) : "memory")
__device__ __forceinline__ void cp16(uint32_t dst, const void* src) {
    asm volatile("cp.async.cg.shared.global [%0], [%1], 16;" :: "r"(dst), "l"(src) : "memory");
}
// generic staged tile (gemm2): 256 threads
__device__ __forceinline__ void stage_tile(uint32_t dstBase, const char* src, size_t rowB, int nRows) {
    const int units = nRows * 8;
    for (int u = threadIdx.x; u < units; u += 256) {
        int r = u >> 3, cu = u & 7;
        cp16(dstBase + (uint32_t)(((r << 3) + (cu ^ (r & 7))) << 4), src + (size_t)r * rowB + (cu << 4));
    }
}

#define LDSM4(a, addr) asm volatile( \
    "ldmatrix.sync.aligned.m8n8.x4.shared.b16 {%0,%1,%2,%3}, [%4];" \
    : "=r"((a)[0]), "=r"((a)[1]), "=r"((a)[2]), "=r"((a)[3]) : "r"(addr))
#define LDSM2(b, addr) asm volatile( \
    "ldmatrix.sync.aligned.m8n8.x2.shared.b16 {%0,%1}, [%2];" \
    : "=r"((b)[0]), "=r"((b)[1]) : "r"(addr))
#define MMA(c, a, b0, b1) asm volatile( \
    "mma.sync.aligned.m16n8k16.row.col.f32.bf16.bf16.f32 " \
    "{%0,%1,%2,%3},{%4,%5,%6,%7},{%8,%9},{%0,%1,%2,%3};" \
    : "+f"((c)[0]), "+f"((c)[1]), "+f"((c)[2]), "+f"((c)[3]) \
    : "r"((a)[0]), "r"((a)[1]), "r"((a)[2]), "r"((a)[3]), "r"(b0), "r"(b1))

// ============ prep ============
// fused x+w split: indices [0, 4M) -> x, [4M, 6M) -> w
__global__ void prep_xw(const float* __restrict__ x, const float* __restrict__ W) {
    int i = blockIdx.x * 256 + threadIdx.x;
    if (i < B_TOT * D_DIM) {
        float v = x[i];
        __nv_bfloat16 h = __float2bfloat16(v);
        g_xh[i] = h;
        g_xl[i] = __float2bfloat16(v - __bfloat162float(h));
    } else {
        int j = i - B_TOT * D_DIM;
        int row = j >> 9, k = j & 511, t = row >> 6, n = row & 63;
        float v = (n < N_NODES) ? W[((size_t)t * N_NODES + n) * D_DIM + k] : 0.f;
        __nv_bfloat16 h = __float2bfloat16(v);
        g_wh[j] = h;
        g_wl[j] = __float2bfloat16(v - __bfloat162float(h));
    }
}
__global__ void prep_m(const float* __restrict__ ll, const float* __restrict__ tw) {
    int row = blockIdx.x * 8 + (threadIdx.x >> 5);   // t*64 + l
    int lane = threadIdx.x & 31;
    const float* src = ll + (size_t)row * C_CLASSES;
    float v[4];
#pragma unroll
    for (int q = 0; q < 4; ++q) { int c = lane + 32 * q; v[q] = (c < C_CLASSES) ? src[c] : -1e30f; }
    float mx = fmaxf(fmaxf(v[0], v[1]), fmaxf(v[2], v[3]));
#pragma unroll
    for (int o = 16; o; o >>= 1) mx = fmaxf(mx, __shfl_xor_sync(~0u, mx, o));
    float e[4], s = 0.f;
#pragma unroll
    for (int q = 0; q < 4; ++q) { int c = lane + 32 * q; e[q] = (c < C_CLASSES) ? __expf(v[q] - mx) : 0.f; s += e[q]; }
#pragma unroll
    for (int o = 16; o; o >>= 1) s += __shfl_xor_sync(~0u, s, o);
    float scale = tw[row >> 6] / s;
#pragma unroll
    for (int q = 0; q < 4; ++q) {
        int c = lane + 32 * q;
        if (c < C_CLASSES) g_m[(size_t)c * NTN + row] = __float2bfloat16(e[q] * scale);
    }
}

// ============ GEMM1 fused 3-pass + sigmoid + leaf product (R12, unchanged) ============
#define G1_AOFF 1024
#define G1_ASL  16384
#define G1_BOFF (1024 + 3 * G1_ASL)          // 50176
#define G1_BSL  32768
#define G1_SMEM (G1_BOFF + 2 * G1_BSL)       // 115712

__global__ void __launch_bounds__(256, 2) gemm1_kernel(const float* __restrict__ bias) {
    extern __shared__ char smem[];
    const uint32_t sb = s2u(smem);
    const int tid = threadIdx.x, wid = tid >> 5, lane = tid & 31;
    const int b0 = blockIdx.x * 128, ntb = blockIdx.y;

    if (tid < 126) {
        int tt = tid / 63, n = tid % 63;
        ((float*)smem)[tt * 64 + n] = bias[(ntb * 2 + tt) * N_NODES + n];
    }

    const char* srcXh = (const char*)g_xh + (size_t)b0 * 1024;
    const char* srcXl = (const char*)g_xl + (size_t)b0 * 1024;
    const char* srcWh = (const char*)g_wh + (size_t)(ntb * 128) * 1024;
    const char* srcWl = (const char*)g_wl + (size_t)(ntb * 128) * 1024;

#define STAGE_A(hc, slotB) do {                                                    \
    _Pragma("unroll") for (int _i = 0; _i < 2; ++_i) {                             \
        int _id = tid + _i * 256, _m = _id >> 2, _u = _id & 3;                     \
        uint32_t _d = (uint32_t)(_m * 64 + ((_u ^ ((_m >> 1) & 3)) << 4));         \
        size_t _s = (size_t)_m * 1024 + (size_t)(hc) * 64 + (_u << 4);             \
        cp16((slotB) + _d, srcXh + _s);                                            \
        cp16((slotB) + 8192 + _d, srcXl + _s);                                     \
    } } while (0)
#define STAGE_B(c, slotB) do {                                                     \
    _Pragma("unroll") for (int _i = 0; _i < 4; ++_i) {                             \
        int _id = tid + _i * 256, _r = _id >> 3, _cu = _id & 7;                    \
        uint32_t _d = (uint32_t)(_r * 128 + ((_cu ^ (_r & 7)) << 4));              \
        size_t _s = (size_t)_r * 1024 + (size_t)(c) * 128 + (_cu << 4);            \
        cp16((slotB) + _d, srcWh + _s);                                            \
        cp16((slotB) + 16384 + _d, srcWl + _s);                                    \
    } } while (0)

    const int wm = wid & 3, wn = wid >> 2;
    const int m0w = wm * 32, n0w = wn * 64;
    const uint32_t sx = lane & 7;
    const uint32_t bKh = (lane >> 3) & 1;
    const uint32_t kh4 = ((lane >> 4) & 1) << 4;
    uint32_t PA[2];
#pragma unroll
    for (int mt = 0; mt < 2; ++mt) {
        int row = m0w + mt * 16 + (lane & 15);
        PA[mt] = (uint32_t)(row * 64 + (((row >> 1) & 3) << 4));
    }
    uint32_t rB[4];
#pragma unroll
    for (int np = 0; np < 4; ++np)
        rB[np] = (uint32_t)(n0w + np * 16 + (lane & 7) + ((lane & 16) >> 1)) * 128;

    float acc[2][8][4];
#pragma unroll
    for (int mt = 0; mt < 2; ++mt)
#pragma unroll
        for (int nf = 0; nf < 8; ++nf)
#pragma unroll
            for (int q = 0; q < 4; ++q) acc[mt][nf][q] = 0.f;

    STAGE_A(0, sb + G1_AOFF);
    STAGE_B(0, sb + G1_BOFF);
    CP_COMMIT();
    STAGE_A(1, sb + G1_AOFF + G1_ASL);
    CP_COMMIT();

    uint32_t aComp = sb + G1_AOFF;
    uint32_t aStage = sb + G1_AOFF + 2 * G1_ASL;
    const uint32_t aLo = sb + G1_AOFF, aHi = sb + G1_AOFF + 2 * G1_ASL;

#pragma unroll 1
    for (int h = 0; h < 16; ++h) {
        CP_WAIT(1);
        __syncthreads();
        if (h <= 13) STAGE_A(h + 2, aStage);
        if (!(h & 1) && h <= 12) STAGE_B((h >> 1) + 1, sb + G1_BOFF + ((((h >> 1) + 1) & 1) ? G1_BSL : 0));
        CP_COMMIT();

        const uint32_t Ah = aComp, Al = aComp + 8192;
        const uint32_t Bb = sb + G1_BOFF + (((h >> 1) & 1) ? G1_BSL : 0);
        const uint32_t kbase = (uint32_t)(h & 1) * 2;

#pragma unroll
        for (int ks = 0; ks < 2; ++ks) {
            const uint32_t uoA = (((uint32_t)ks << 5) + kh4);
            uint32_t ah[2][4], al[2][4];
            LDSM4(ah[0], Ah + (PA[0] ^ uoA));
            LDSM4(ah[1], Ah + (PA[1] ^ uoA));
            LDSM4(al[0], Al + (PA[0] ^ uoA));
            LDSM4(al[1], Al + (PA[1] ^ uoA));

            const uint32_t koB = (((kbase + (uint32_t)ks) * 2 + bKh) ^ sx) << 4;
            uint32_t bh[4][4];
#pragma unroll
            for (int np = 0; np < 4; ++np) LDSM4(bh[np], Bb + rB[np] + koB);
#pragma unroll
            for (int mt = 0; mt < 2; ++mt)
#pragma unroll
                for (int np = 0; np < 4; ++np) {
                    MMA(acc[mt][np * 2],     ah[mt], bh[np][0], bh[np][1]);
                    MMA(acc[mt][np * 2 + 1], ah[mt], bh[np][2], bh[np][3]);
                }
#pragma unroll
            for (int mt = 0; mt < 2; ++mt)
#pragma unroll
                for (int np = 0; np < 4; ++np) {
                    MMA(acc[mt][np * 2],     al[mt], bh[np][0], bh[np][1]);
                    MMA(acc[mt][np * 2 + 1], al[mt], bh[np][2], bh[np][3]);
                }
            uint32_t bl[4][4];
#pragma unroll
            for (int np = 0; np < 4; ++np) LDSM4(bl[np], Bb + 16384 + rB[np] + koB);
#pragma unroll
            for (int mt = 0; mt < 2; ++mt)
#pragma unroll
                for (int np = 0; np < 4; ++np) {
                    MMA(acc[mt][np * 2],     ah[mt], bl[np][0], bl[np][1]);
                    MMA(acc[mt][np * 2 + 1], ah[mt], bl[np][2], bl[np][3]);
                }
        }
        aComp  = (aComp  == aHi) ? aLo : aComp + G1_ASL;
        aStage = (aStage == aHi) ? aLo : aStage + G1_ASL;
    }

    float* dec = (float*)(smem + G1_AOFF);        // 128 x pitch65 f32
    const float* bsm = (const float*)smem;
    const int r4 = lane >> 2, c2 = (lane & 3) * 2;

#pragma unroll 1
    for (int t = 0; t < 2; ++t) {
        __syncthreads();
        if (wn == t) {
#pragma unroll
            for (int mt = 0; mt < 2; ++mt)
#pragma unroll
                for (int nf = 0; nf < 8; ++nf) {
                    int row = m0w + mt * 16 + r4, col = nf * 8 + c2;
                    dec[row * 65 + col]           = acc[mt][nf][0];
                    dec[row * 65 + col + 1]       = acc[mt][nf][1];
                    dec[(row + 8) * 65 + col]     = acc[mt][nf][2];
                    dec[(row + 8) * 65 + col + 1] = acc[mt][nf][3];
                }
        }
        __syncthreads();
        {
            const int row = tid & 127, hh = tid >> 7;
            const float* dr = dec + row * 65;
            const float* bs = bsm + t * 64;
            float dc[63];
#pragma unroll
            for (int n = 0; n < 63; ++n)
                dc[n] = __fdividef(1.f, 1.f + __expf(-(dr[n] + bs[n])));
            float p[32];
            p[0] = hh ? dc[0] : (1.f - dc[0]);
#pragma unroll
            for (int d = 1; d < 6; ++d)
#pragma unroll
                for (int i = (1 << (d - 1)) - 1; i >= 0; --i) {
                    float v = dc[(1 << d) - 1 + hh * (1 << (d - 1)) + i], pi = p[i];
                    p[2 * i + 1] = pi * v;
                    p[2 * i]     = pi * (1.f - v);
                }
            __nv_bfloat16 ob[32];
#pragma unroll
            for (int l = 0; l < 32; ++l) ob[l] = __float2bfloat16(p[l]);
            uint4* dst = (uint4*)(g_lp + (size_t)(b0 + row) * NTN + (ntb * 2 + t) * 64 + hh * 32);
            const uint4* srcv = (const uint4*)ob;
#pragma unroll
            for (int q = 0; q < 4; ++q) dst[q] = srcv[q];
        }
    }
}

// ============ GEMM2: out = lp @ M^T, full K per CTA, 4-stage ring ============
// grid 128: 64 batch rows x 128 classes (>=100 dropped). 8 warps (2m x 4n), warp 32x32.
// K = 4096 = 64 segments x 64 k.
#define G2_SOFF 1024
#define G2_BUF  24576                       // A 8KB + B 16KB
#define G2_SMEM (G2_SOFF + 4 * G2_BUF)      // 99328
#define G2_NSEG 64

__global__ void __launch_bounds__(256) gemm2_kernel(float* __restrict__ out) {
    extern __shared__ char smem[];
    const uint32_t sb = s2u(smem);
    const int tid = threadIdx.x, wid = tid >> 5, lane = tid & 31;
    const int b0 = blockIdx.x * 64;

    const char* Ag = (const char*)g_lp + (size_t)b0 * 8192;
    const char* Bg = (const char*)g_m;

#define G2_SEG(seg) do { uint32_t _b = sb + G2_SOFF + ((seg) & 3) * G2_BUF; \
    stage_tile(_b, Ag + (size_t)(seg) * 128, 8192, 64); \
    stage_tile(_b + 8192, Bg + (size_t)(seg) * 128, 8192, 128); \
    CP_COMMIT(); } while (0)

    const int wm = wid >> 2, wn = wid & 3;
    const int m0w = wm * 32, n0w = wn * 32;
    const uint32_t sx = lane & 7;
    const uint32_t aKh = (lane >> 4) & 1, bKh = (lane >> 3) & 1;
    uint32_t rA[2], rB[4];
#pragma unroll
    for (int mt = 0; mt < 2; ++mt) rA[mt] = (uint32_t)(m0w + mt * 16 + (lane & 15)) * 128;
#pragma unroll
    for (int nt = 0; nt < 4; ++nt) rB[nt] = (uint32_t)(n0w + nt * 8 + (lane & 7)) * 128;

    float acc[2][4][4];
#pragma unroll
    for (int mt = 0; mt < 2; ++mt)
#pragma unroll
        for (int nt = 0; nt < 4; ++nt)
#pragma unroll
            for (int q = 0; q < 4; ++q) acc[mt][nt][q] = 0.f;

    G2_SEG(0); G2_SEG(1); G2_SEG(2);
#pragma unroll 1
    for (int seg = 0; seg < G2_NSEG; ++seg) {
        if (seg <= G2_NSEG - 3)      { CP_WAIT(2); }
        else if (seg == G2_NSEG - 2) { CP_WAIT(1); }
        else                         { CP_WAIT(0); }
        __syncthreads();
        if (seg + 3 < G2_NSEG) G2_SEG(seg + 3);   // slot (seg+3)&3: consumers done at seg-1

        uint32_t Ab = sb + G2_SOFF + (seg & 3) * G2_BUF;
        uint32_t Bb = Ab + 8192;
#pragma unroll
        for (int ks = 0; ks < 4; ++ks) {
            uint32_t a[2][4], b[4][2];
#pragma unroll
            for (int mt = 0; mt < 2; ++mt)
                LDSM4(a[mt], Ab + rA[mt] + ((((uint32_t)ks * 2 + aKh) ^ sx) << 4));
#pragma unroll
            for (int nt = 0; nt < 4; ++nt)
                LDSM2(b[nt], Bb + rB[nt] + ((((uint32_t)ks * 2 + bKh) ^ sx) << 4));
#pragma unroll
            for (int mt = 0; mt < 2; ++mt)
#pragma unroll
                for (int nt = 0; nt < 4; ++nt)
                    MMA(acc[mt][nt], a[mt], b[nt][0], b[nt][1]);
        }
    }

    {
        const int r = lane >> 2, c2 = (lane & 3) * 2;
#pragma unroll
        for (int mt = 0; mt < 2; ++mt)
#pragma unroll
            for (int nt = 0; nt < 4; ++nt) {
                int row = b0 + m0w + mt * 16 + r;
                int col = n0w + nt * 8 + c2;
                if (col < C_CLASSES) {
                    out[(size_t)row * C_CLASSES + col]       = acc[mt][nt][0];
                    out[(size_t)(row + 8) * C_CLASSES + col] = acc[mt][nt][2];
                }
                if (col + 1 < C_CLASSES) {
                    out[(size_t)row * C_CLASSES + col + 1]       = acc[mt][nt][1];
                    out[(size_t)(row + 8) * C_CLASSES + col + 1] = acc[mt][nt][3];
                }
            }
    }
}

// ============ launch ============
extern "C" void kernel_launch(void* const* d_in, const int* in_sizes, int n_in,
                              void* d_out, int out_size) {
    const float* x    = (const float*)d_in[0];
    const float* W    = (const float*)d_in[1];
    const float* bias = (const float*)d_in[2];
    const float* ll   = (const float*)d_in[3];
    const float* tw   = (const float*)d_in[4];
    float* out = (float*)d_out;

    cudaFuncSetAttribute(gemm1_kernel, cudaFuncAttributeMaxDynamicSharedMemorySize, G1_SMEM);
    cudaFuncSetAttribute(gemm2_kernel, cudaFuncAttributeMaxDynamicSharedMemorySize, G2_SMEM);

    prep_xw<<<(B_TOT * D_DIM + NTN * D_DIM) / 256, 256>>>(x, W);
    prep_m<<<512, 256>>>(ll, tw);
    gemm1_kernel<<<dim3(64, 32), 256, G1_SMEM>>>(bias);
    gemm2_kernel<<<128, 256, G2_SMEM>>>(out);
}